// round 1
// baseline (speedup 1.0000x reference)
#include <cuda_runtime.h>
#include <math.h>

#define BB 4
#define SSEQ 2048
#define DMODEL 1024
#define NHEAD 16
#define HDIM 64

// Scratch (static device globals — no allocation in kernel_launch)
__device__ float g_Q[(size_t)BB * NHEAD * SSEQ * HDIM];
__device__ float g_K[(size_t)BB * NHEAD * SSEQ * HDIM];
__device__ float g_V[(size_t)BB * NHEAD * SSEQ * HDIM];
__device__ float g_attn[(size_t)BB * SSEQ * DMODEL];

#define TSTR 132  // padded row stride (floats), 132*4 bytes keeps 16B alignment

// ---------------------------------------------------------------------------
// C[128x128 tile] = A[M,1024] @ W[1024,1024] + bias ; optional head-permute
// 256 threads, each computes 8x8 split as (4+4)x(4+4) for conflict-free LDS.128
// ---------------------------------------------------------------------------
__global__ void __launch_bounds__(256) gemm128(
    const float* __restrict__ A, const float* __restrict__ W,
    const float* __restrict__ bias, float* __restrict__ C, int permute)
{
    __shared__ float As[16 * TSTR];  // As[k][m], transposed A tile
    __shared__ float Bs[16 * TSTR];  // Bs[k][n]
    const int tid = threadIdx.x;
    const int tx = tid & 15, ty = tid >> 4;
    const int tx4 = tx * 4, ty4 = ty * 4;
    const int m0 = blockIdx.y * 128, n0 = blockIdx.x * 128;

    float acc[8][8];
#pragma unroll
    for (int i = 0; i < 8; i++)
#pragma unroll
        for (int j = 0; j < 8; j++) acc[i][j] = 0.f;

    for (int kt = 0; kt < DMODEL; kt += 16) {
        __syncthreads();
        // A tile: 128 rows x 16 k-cols, store transposed
#pragma unroll
        for (int l = 0; l < 2; l++) {
            int q = l * 256 + tid;
            int row = q >> 2, c4 = q & 3;
            float4 v = *(const float4*)(A + (size_t)(m0 + row) * DMODEL + kt + c4 * 4);
            As[(c4 * 4 + 0) * TSTR + row] = v.x;
            As[(c4 * 4 + 1) * TSTR + row] = v.y;
            As[(c4 * 4 + 2) * TSTR + row] = v.z;
            As[(c4 * 4 + 3) * TSTR + row] = v.w;
        }
        // B tile: 16 k-rows x 128 n-cols, direct
#pragma unroll
        for (int l = 0; l < 2; l++) {
            int q = l * 256 + tid;
            int row = q >> 5, c4 = q & 31;
            *(float4*)&Bs[row * TSTR + c4 * 4] =
                *(const float4*)(W + (size_t)(kt + row) * DMODEL + n0 + c4 * 4);
        }
        __syncthreads();
#pragma unroll 4
        for (int k = 0; k < 16; k++) {
            float a[8], b[8];
            *(float4*)(a)     = *(float4*)&As[k * TSTR + ty4];
            *(float4*)(a + 4) = *(float4*)&As[k * TSTR + 64 + ty4];
            *(float4*)(b)     = *(float4*)&Bs[k * TSTR + tx4];
            *(float4*)(b + 4) = *(float4*)&Bs[k * TSTR + 64 + tx4];
#pragma unroll
            for (int i = 0; i < 8; i++)
#pragma unroll
                for (int j = 0; j < 8; j++)
                    acc[i][j] = fmaf(a[i], b[j], acc[i][j]);
        }
    }

    int rr[8], cc[8];
#pragma unroll
    for (int i = 0; i < 4; i++) {
        rr[i] = m0 + ty4 + i; rr[i + 4] = m0 + 64 + ty4 + i;
        cc[i] = n0 + tx4 + i; cc[i + 4] = n0 + 64 + tx4 + i;
    }
#pragma unroll
    for (int i = 0; i < 8; i++) {
#pragma unroll
        for (int j = 0; j < 8; j++) {
            float v = acc[i][j] + bias[cc[j]];
            if (permute) {  // (m,n) -> [b][h][s][d]
                int n = cc[j], hh = n >> 6, dd = n & 63;
                int m = rr[i], bb = m >> 11, ss = m & 2047;
                C[(((size_t)(bb * NHEAD + hh)) * SSEQ + ss) * HDIM + dd] = v;
            } else {
                C[(size_t)rr[i] * DMODEL + cc[j]] = v;
            }
        }
    }
}

// ---------------------------------------------------------------------------
// Flash-style attention: one block per (qblock=128 rows, head, batch).
// 256 threads; scores 128x128 per KV block, online softmax, O accum 128x64.
// ---------------------------------------------------------------------------
__global__ void __launch_bounds__(256) attn_kernel(
    const float* __restrict__ Q, const float* __restrict__ K,
    const float* __restrict__ V, float* __restrict__ Aout)
{
    extern __shared__ float sm[];
    float* Qts = sm;                    // [64][TSTR]  Q^T (d-major)
    float* Kts = Qts + 64 * TSTR;       // [64][TSTR]  K^T
    float* Vs  = Kts + 64 * TSTR;       // [128][64]
    float* Ps  = Vs + 128 * 64;         // [128][TSTR] exp(scores)

    const int tid = threadIdx.x;
    const int tx = tid & 15, ty = tid >> 4;
    const int tx4 = tx * 4, ty4 = ty * 4;
    const int b = blockIdx.z, h = blockIdx.y, qb = blockIdx.x;
    const size_t bh = (size_t)b * NHEAD + h;

    // Load Q tile (transpose into Qts)
    const float* Qg = Q + (bh * SSEQ + (size_t)qb * 128) * HDIM;
#pragma unroll
    for (int l = 0; l < 8; l++) {
        int q = l * 256 + tid;
        int row = q >> 4, c4 = q & 15;
        float4 v = *(const float4*)(Qg + row * HDIM + c4 * 4);
        Qts[(c4 * 4 + 0) * TSTR + row] = v.x;
        Qts[(c4 * 4 + 1) * TSTR + row] = v.y;
        Qts[(c4 * 4 + 2) * TSTR + row] = v.z;
        Qts[(c4 * 4 + 3) * TSTR + row] = v.w;
    }

    int lr[8];
#pragma unroll
    for (int i = 0; i < 4; i++) { lr[i] = ty4 + i; lr[i + 4] = 64 + ty4 + i; }

    float m_run[8], l_run[8], o[8][4];
#pragma unroll
    for (int i = 0; i < 8; i++) {
        m_run[i] = -INFINITY; l_run[i] = 0.f;
        o[i][0] = o[i][1] = o[i][2] = o[i][3] = 0.f;
    }

    for (int kb = 0; kb < 16; kb++) {
        __syncthreads();  // previous P@V reads done before overwriting K/V/P
        const float* Kg = K + (bh * SSEQ + (size_t)kb * 128) * HDIM;
        const float* Vg = V + (bh * SSEQ + (size_t)kb * 128) * HDIM;
#pragma unroll
        for (int l = 0; l < 8; l++) {
            int q = l * 256 + tid;
            int row = q >> 4, c4 = q & 15;
            float4 v = *(const float4*)(Kg + row * HDIM + c4 * 4);
            Kts[(c4 * 4 + 0) * TSTR + row] = v.x;
            Kts[(c4 * 4 + 1) * TSTR + row] = v.y;
            Kts[(c4 * 4 + 2) * TSTR + row] = v.z;
            Kts[(c4 * 4 + 3) * TSTR + row] = v.w;
            float4 w = *(const float4*)(Vg + row * HDIM + c4 * 4);
            *(float4*)&Vs[row * 64 + c4 * 4] = w;
        }
        __syncthreads();

        // S = Q @ K^T  (128x128, each thread 8x8 split 4+4)
        float s_[8][8];
#pragma unroll
        for (int i = 0; i < 8; i++)
#pragma unroll
            for (int j = 0; j < 8; j++) s_[i][j] = 0.f;
#pragma unroll 8
        for (int d = 0; d < 64; d++) {
            float a[8], kk[8];
            *(float4*)(a)      = *(float4*)&Qts[d * TSTR + ty4];
            *(float4*)(a + 4)  = *(float4*)&Qts[d * TSTR + 64 + ty4];
            *(float4*)(kk)     = *(float4*)&Kts[d * TSTR + tx4];
            *(float4*)(kk + 4) = *(float4*)&Kts[d * TSTR + 64 + tx4];
#pragma unroll
            for (int i = 0; i < 8; i++)
#pragma unroll
                for (int j = 0; j < 8; j++)
                    s_[i][j] = fmaf(a[i], kk[j], s_[i][j]);
        }

        // Online softmax per row (row reduce across the 16 tx lanes = half-warp)
#pragma unroll
        for (int i = 0; i < 8; i++) {
            float mx = -INFINITY;
#pragma unroll
            for (int j = 0; j < 8; j++) { s_[i][j] *= 0.125f; mx = fmaxf(mx, s_[i][j]); }
#pragma unroll
            for (int off = 1; off < 16; off <<= 1)
                mx = fmaxf(mx, __shfl_xor_sync(0xffffffffu, mx, off));
            float m_new = fmaxf(m_run[i], mx);
            float alpha = __expf(m_run[i] - m_new);
            float lsum = 0.f;
#pragma unroll
            for (int j = 0; j < 8; j++) { s_[i][j] = __expf(s_[i][j] - m_new); lsum += s_[i][j]; }
#pragma unroll
            for (int off = 1; off < 16; off <<= 1)
                lsum += __shfl_xor_sync(0xffffffffu, lsum, off);
            l_run[i] = l_run[i] * alpha + lsum;
            m_run[i] = m_new;
            o[i][0] *= alpha; o[i][1] *= alpha; o[i][2] *= alpha; o[i][3] *= alpha;
            *(float4*)&Ps[lr[i] * TSTR + tx4] =
                make_float4(s_[i][0], s_[i][1], s_[i][2], s_[i][3]);
            *(float4*)&Ps[lr[i] * TSTR + 64 + tx4] =
                make_float4(s_[i][4], s_[i][5], s_[i][6], s_[i][7]);
        }
        __syncthreads();

        // O += P @ V  (each thread: 8 rows x 4 cols at tx*4)
#pragma unroll 4
        for (int c4i = 0; c4i < 32; c4i++) {
            float4 v0 = *(float4*)&Vs[(c4i * 4 + 0) * 64 + tx4];
            float4 v1 = *(float4*)&Vs[(c4i * 4 + 1) * 64 + tx4];
            float4 v2 = *(float4*)&Vs[(c4i * 4 + 2) * 64 + tx4];
            float4 v3 = *(float4*)&Vs[(c4i * 4 + 3) * 64 + tx4];
#pragma unroll
            for (int i = 0; i < 8; i++) {
                float4 p = *(float4*)&Ps[lr[i] * TSTR + c4i * 4];
                o[i][0] = fmaf(p.x, v0.x, fmaf(p.y, v1.x, fmaf(p.z, v2.x, fmaf(p.w, v3.x, o[i][0]))));
                o[i][1] = fmaf(p.x, v0.y, fmaf(p.y, v1.y, fmaf(p.z, v2.y, fmaf(p.w, v3.y, o[i][1]))));
                o[i][2] = fmaf(p.x, v0.z, fmaf(p.y, v1.z, fmaf(p.z, v2.z, fmaf(p.w, v3.z, o[i][2]))));
                o[i][3] = fmaf(p.x, v0.w, fmaf(p.y, v1.w, fmaf(p.z, v2.w, fmaf(p.w, v3.w, o[i][3]))));
            }
        }
    }

    // Normalize and write to [b][s][h*64+col] (concat layout)
#pragma unroll
    for (int i = 0; i < 8; i++) {
        float inv = 1.f / l_run[i];
        float4 r = make_float4(o[i][0] * inv, o[i][1] * inv, o[i][2] * inv, o[i][3] * inv);
        int srow = qb * 128 + lr[i];
        *(float4*)&Aout[((size_t)b * SSEQ + srow) * DMODEL + h * HDIM + tx4] = r;
    }
}

extern "C" void kernel_launch(void* const* d_in, const int* in_sizes, int n_in,
                              void* d_out, int out_size) {
    const float* X  = (const float*)d_in[0];
    const float* Wq = (const float*)d_in[1];
    const float* bq = (const float*)d_in[2];
    const float* Wk = (const float*)d_in[3];
    const float* bk = (const float*)d_in[4];
    const float* Wv = (const float*)d_in[5];
    const float* bv = (const float*)d_in[6];
    const float* Wo = (const float*)d_in[7];
    const float* bo = (const float*)d_in[8];
    float* out = (float*)d_out;

    void *qp, *kp, *vp, *ap;
    cudaGetSymbolAddress(&qp, g_Q);
    cudaGetSymbolAddress(&kp, g_K);
    cudaGetSymbolAddress(&vp, g_V);
    cudaGetSymbolAddress(&ap, g_attn);

    const int smem = (2 * 64 * TSTR + 128 * 64 + 128 * TSTR) * (int)sizeof(float);
    cudaFuncSetAttribute(attn_kernel, cudaFuncAttributeMaxDynamicSharedMemorySize, smem);

    dim3 gg(DMODEL / 128, (BB * SSEQ) / 128, 1);  // (8, 64)
    gemm128<<<gg, 256>>>(X, Wq, bq, (float*)qp, 1);
    gemm128<<<gg, 256>>>(X, Wk, bk, (float*)kp, 1);
    gemm128<<<gg, 256>>>(X, Wv, bv, (float*)vp, 1);
    attn_kernel<<<dim3(SSEQ / 128, NHEAD, BB), 256, smem>>>(
        (const float*)qp, (const float*)kp, (const float*)vp, (float*)ap);
    gemm128<<<gg, 256>>>((const float*)ap, Wo, bo, out, 0);
}

// round 3
// speedup vs baseline: 2.1813x; 2.1813x over previous
#include <cuda_runtime.h>
#include <math.h>
#include <cstdint>

#define BB 4
#define SSEQ 2048
#define DMODEL 1024
#define NHEAD 16
#define HDIM 64

// Scratch (static device globals — no allocation in kernel_launch)
__device__ float g_Q[(size_t)BB * NHEAD * SSEQ * HDIM];
__device__ float g_K[(size_t)BB * NHEAD * SSEQ * HDIM];
__device__ float g_V[(size_t)BB * NHEAD * SSEQ * HDIM];
__device__ float g_attn[(size_t)BB * SSEQ * DMODEL];

// ---------------------------------------------------------------------------
// Helpers
// ---------------------------------------------------------------------------
__device__ __forceinline__ uint32_t f2tf_u(float f) {
    uint32_t u;
    asm("cvt.rna.tf32.f32 %0, %1;" : "=r"(u) : "f"(f));
    return u;
}
__device__ __forceinline__ float f2tf(float f) { return __uint_as_float(f2tf_u(f)); }

// D += A(16x8 row) * B(8x8 col), tf32, fp32 accum
__device__ __forceinline__ void mma8(float* c, const uint32_t* a, const uint32_t* b) {
    asm volatile(
        "mma.sync.aligned.m16n8k8.row.col.f32.tf32.tf32.f32 "
        "{%0,%1,%2,%3}, {%4,%5,%6,%7}, {%8,%9}, {%0,%1,%2,%3};"
        : "+f"(c[0]), "+f"(c[1]), "+f"(c[2]), "+f"(c[3])
        : "r"(a[0]), "r"(a[1]), "r"(a[2]), "r"(a[3]), "r"(b[0]), "r"(b[1]));
}

// exp(x) for x <= 0, FFMA-pipe only (no MUFU). ~1e-6 rel acc.
__device__ __forceinline__ float fexp(float x) {
    x = fmaxf(x, -80.f);
    float y = x * 1.4426950408889634f;
    float t = y + 12582912.f;                    // RN to integer (magic)
    int   ki = __float_as_int(t) - 0x4B400000;
    float f = y - (t - 12582912.f);              // frac in [-0.5, 0.5]
    float r = fmaf(f, 0.0018775767f, 0.0089893397f);
    r = fmaf(r, f, 0.0558263180f);
    r = fmaf(r, f, 0.2401536125f);
    r = fmaf(r, f, 0.6931471825f);
    r = fmaf(r, f, 1.0f);
    return __int_as_float(__float_as_int(r) + (ki << 23));
}

// ---------------------------------------------------------------------------
// tf32 tensor GEMM: C[128x128/block] = A[M,1024] @ W[1024,1024] + bias
// 8 warps (2m x 4n), warp tile 64x32, K-chunk 16, double-buffered smem.
// Smem strides chosen conflict-free for m16n8k8 fragment loads:
//   A stride 20 (20 mod 32 = 20 -> bases {0,20,8,28,16,4,24,12} all distinct)
//   B stride 132 (132 mod 32 = 4 -> 4*tig + gID all distinct)
// ---------------------------------------------------------------------------
#define ASTR 20
#define BSTR 132

__global__ void __launch_bounds__(256) gemm_tc(
    const float* __restrict__ A, const float* __restrict__ W,
    const float* __restrict__ bias, float* __restrict__ C, int permute)
{
    __shared__ float As[2][128 * ASTR];
    __shared__ float Bs[2][16 * BSTR];

    const int tid = threadIdx.x, lane = tid & 31, wid = tid >> 5;
    const int gID = lane >> 2, tig = lane & 3;
    const int wm = wid >> 2, wn = wid & 3;
    const int m0 = blockIdx.y * 128, n0 = blockIdx.x * 128;

    const float* Ag = A + (size_t)m0 * DMODEL;
    const float* Bg = W + n0;

    float acc[4][4][4];
#pragma unroll
    for (int mt = 0; mt < 4; mt++)
#pragma unroll
        for (int nt = 0; nt < 4; nt++)
#pragma unroll
            for (int i = 0; i < 4; i++) acc[mt][nt][i] = 0.f;

    const int ar = tid >> 2, ac = (tid & 3) * 4;   // A: rows ar, ar+64
    const int br = tid >> 5, bc = (tid & 31) * 4;  // B: rows br, br+8

    float4 ra0, ra1, rb0, rb1;
    // prologue: load + store chunk 0
    ra0 = *(const float4*)(Ag + (size_t)ar * DMODEL + ac);
    ra1 = *(const float4*)(Ag + (size_t)(ar + 64) * DMODEL + ac);
    rb0 = *(const float4*)(Bg + (size_t)br * DMODEL + bc);
    rb1 = *(const float4*)(Bg + (size_t)(br + 8) * DMODEL + bc);
    {
        float* pa = As[0]; float* pb = Bs[0];
        pa[ar * ASTR + ac + 0] = f2tf(ra0.x); pa[ar * ASTR + ac + 1] = f2tf(ra0.y);
        pa[ar * ASTR + ac + 2] = f2tf(ra0.z); pa[ar * ASTR + ac + 3] = f2tf(ra0.w);
        pa[(ar + 64) * ASTR + ac + 0] = f2tf(ra1.x); pa[(ar + 64) * ASTR + ac + 1] = f2tf(ra1.y);
        pa[(ar + 64) * ASTR + ac + 2] = f2tf(ra1.z); pa[(ar + 64) * ASTR + ac + 3] = f2tf(ra1.w);
        pb[br * BSTR + bc + 0] = f2tf(rb0.x); pb[br * BSTR + bc + 1] = f2tf(rb0.y);
        pb[br * BSTR + bc + 2] = f2tf(rb0.z); pb[br * BSTR + bc + 3] = f2tf(rb0.w);
        pb[(br + 8) * BSTR + bc + 0] = f2tf(rb1.x); pb[(br + 8) * BSTR + bc + 1] = f2tf(rb1.y);
        pb[(br + 8) * BSTR + bc + 2] = f2tf(rb1.z); pb[(br + 8) * BSTR + bc + 3] = f2tf(rb1.w);
    }
    __syncthreads();

    for (int ch = 0; ch < 64; ++ch) {
        const int buf = ch & 1;
        if (ch < 63) {
            const int kt = (ch + 1) * 16;
            ra0 = *(const float4*)(Ag + (size_t)ar * DMODEL + kt + ac);
            ra1 = *(const float4*)(Ag + (size_t)(ar + 64) * DMODEL + kt + ac);
            rb0 = *(const float4*)(Bg + (size_t)(kt + br) * DMODEL + bc);
            rb1 = *(const float4*)(Bg + (size_t)(kt + br + 8) * DMODEL + bc);
        }
        const float* pa = As[buf];
        const float* pb = Bs[buf];
#pragma unroll
        for (int kk = 0; kk < 2; ++kk) {
            uint32_t af[4][4], bf[4][2];
            const int ci = kk * 8 + tig;
#pragma unroll
            for (int mt = 0; mt < 4; ++mt) {
                const int r = wm * 64 + mt * 16 + gID;
                af[mt][0] = __float_as_uint(pa[r * ASTR + ci]);
                af[mt][1] = __float_as_uint(pa[(r + 8) * ASTR + ci]);
                af[mt][2] = __float_as_uint(pa[r * ASTR + ci + 4]);
                af[mt][3] = __float_as_uint(pa[(r + 8) * ASTR + ci + 4]);
            }
#pragma unroll
            for (int nt = 0; nt < 4; ++nt) {
                const int cn = wn * 32 + nt * 8 + gID;
                bf[nt][0] = __float_as_uint(pb[ci * BSTR + cn]);
                bf[nt][1] = __float_as_uint(pb[(ci + 4) * BSTR + cn]);
            }
#pragma unroll
            for (int mt = 0; mt < 4; ++mt)
#pragma unroll
                for (int nt = 0; nt < 4; ++nt)
                    mma8(acc[mt][nt], af[mt], bf[nt]);
        }
        if (ch < 63) {
            __syncthreads();
            float* pa2 = As[buf ^ 1]; float* pb2 = Bs[buf ^ 1];
            pa2[ar * ASTR + ac + 0] = f2tf(ra0.x); pa2[ar * ASTR + ac + 1] = f2tf(ra0.y);
            pa2[ar * ASTR + ac + 2] = f2tf(ra0.z); pa2[ar * ASTR + ac + 3] = f2tf(ra0.w);
            pa2[(ar + 64) * ASTR + ac + 0] = f2tf(ra1.x); pa2[(ar + 64) * ASTR + ac + 1] = f2tf(ra1.y);
            pa2[(ar + 64) * ASTR + ac + 2] = f2tf(ra1.z); pa2[(ar + 64) * ASTR + ac + 3] = f2tf(ra1.w);
            pb2[br * BSTR + bc + 0] = f2tf(rb0.x); pb2[br * BSTR + bc + 1] = f2tf(rb0.y);
            pb2[br * BSTR + bc + 2] = f2tf(rb0.z); pb2[br * BSTR + bc + 3] = f2tf(rb0.w);
            pb2[(br + 8) * BSTR + bc + 0] = f2tf(rb1.x); pb2[(br + 8) * BSTR + bc + 1] = f2tf(rb1.y);
            pb2[(br + 8) * BSTR + bc + 2] = f2tf(rb1.z); pb2[(br + 8) * BSTR + bc + 3] = f2tf(rb1.w);
            __syncthreads();
        }
    }

    // epilogue
#pragma unroll
    for (int mt = 0; mt < 4; ++mt) {
        const int r0 = m0 + wm * 64 + mt * 16 + gID;
        const int r1 = r0 + 8;
#pragma unroll
        for (int nt = 0; nt < 4; ++nt) {
            const int c = n0 + wn * 32 + nt * 8 + tig * 2;
            const float b0 = bias[c], b1 = bias[c + 1];
            float2 v0 = make_float2(acc[mt][nt][0] + b0, acc[mt][nt][1] + b1);
            float2 v1 = make_float2(acc[mt][nt][2] + b0, acc[mt][nt][3] + b1);
            if (permute) {
                const int hh = c >> 6, dd = c & 63;
                const int b_0 = r0 >> 11, s_0 = r0 & 2047;
                const int b_1 = r1 >> 11, s_1 = r1 & 2047;
                *(float2*)(C + ((((size_t)(b_0 * NHEAD + hh)) * SSEQ + s_0) * HDIM + dd)) = v0;
                *(float2*)(C + ((((size_t)(b_1 * NHEAD + hh)) * SSEQ + s_1) * HDIM + dd)) = v1;
            } else {
                *(float2*)(C + (size_t)r0 * DMODEL + c) = v0;
                *(float2*)(C + (size_t)r1 * DMODEL + c) = v1;
            }
        }
    }
}

// ---------------------------------------------------------------------------
// Tensor-core flash attention. Block = 128 q-rows x (h, b). 8 warps (2m x 4n).
// S-phase warp tile 64x32 over S(128x128); PV-phase warp tile 64x16 over O(128x64).
// Q prescaled by 0.125 and tf32-rounded. Softmax exp on FMA pipe.
// ---------------------------------------------------------------------------
#define QSTR 68
#define PSTR 132

__global__ void __launch_bounds__(256) attn_tc(
    const float* __restrict__ Q, const float* __restrict__ K,
    const float* __restrict__ V, float* __restrict__ Aout)
{
    extern __shared__ float smf[];
    float* Qs = smf;                  // 128 x QSTR
    float* Ks = Qs + 128 * QSTR;
    float* Vs = Ks + 128 * QSTR;
    float* Ps = Vs + 128 * QSTR;      // 128 x PSTR
    float* mrow = Ps + 128 * PSTR;
    float* lrow = mrow + 128;
    float* arow = lrow + 128;

    const int tid = threadIdx.x, lane = tid & 31, wid = tid >> 5;
    const int gID = lane >> 2, tig = lane & 3;
    const int wm = wid >> 2, wn = wid & 3;
    const int qb = blockIdx.x, h = blockIdx.y, b = blockIdx.z;

    const size_t bh = (size_t)(b * NHEAD + h) * SSEQ;
    const float* Qg = Q + (bh + (size_t)qb * 128) * HDIM;

    const int ldr = tid >> 4, ldc = (tid & 15) * 4;
#pragma unroll
    for (int p = 0; p < 8; ++p) {
        const int r = ldr + p * 16;
        float4 v = *(const float4*)(Qg + (size_t)r * HDIM + ldc);
        Qs[r * QSTR + ldc + 0] = f2tf(v.x * 0.125f);
        Qs[r * QSTR + ldc + 1] = f2tf(v.y * 0.125f);
        Qs[r * QSTR + ldc + 2] = f2tf(v.z * 0.125f);
        Qs[r * QSTR + ldc + 3] = f2tf(v.w * 0.125f);
    }
    if (tid < 128) { mrow[tid] = -INFINITY; lrow[tid] = 0.f; }

    float oacc[4][2][4];
#pragma unroll
    for (int mt = 0; mt < 4; mt++)
#pragma unroll
        for (int nt = 0; nt < 2; nt++)
#pragma unroll
            for (int i = 0; i < 4; i++) oacc[mt][nt][i] = 0.f;

    for (int kb = 0; kb < 16; ++kb) {
        __syncthreads();
        const float* Kg = K + (bh + (size_t)kb * 128) * HDIM;
        const float* Vg = V + (bh + (size_t)kb * 128) * HDIM;
#pragma unroll
        for (int p = 0; p < 8; ++p) {
            const int r = ldr + p * 16;
            float4 kv = *(const float4*)(Kg + (size_t)r * HDIM + ldc);
            float4 vv = *(const float4*)(Vg + (size_t)r * HDIM + ldc);
            Ks[r * QSTR + ldc + 0] = f2tf(kv.x); Ks[r * QSTR + ldc + 1] = f2tf(kv.y);
            Ks[r * QSTR + ldc + 2] = f2tf(kv.z); Ks[r * QSTR + ldc + 3] = f2tf(kv.w);
            Vs[r * QSTR + ldc + 0] = f2tf(vv.x); Vs[r * QSTR + ldc + 1] = f2tf(vv.y);
            Vs[r * QSTR + ldc + 2] = f2tf(vv.z); Vs[r * QSTR + ldc + 3] = f2tf(vv.w);
        }
        __syncthreads();

        // --- S = Q @ K^T ---
        float sacc[4][4][4];
#pragma unroll
        for (int mt = 0; mt < 4; mt++)
#pragma unroll
            for (int nt = 0; nt < 4; nt++)
#pragma unroll
                for (int i = 0; i < 4; i++) sacc[mt][nt][i] = 0.f;

#pragma unroll
        for (int kd = 0; kd < 8; ++kd) {
            uint32_t af[4][4], bf[4][2];
            const int ci = kd * 8 + tig;
#pragma unroll
            for (int mt = 0; mt < 4; ++mt) {
                const int r = wm * 64 + mt * 16 + gID;
                af[mt][0] = __float_as_uint(Qs[r * QSTR + ci]);
                af[mt][1] = __float_as_uint(Qs[(r + 8) * QSTR + ci]);
                af[mt][2] = __float_as_uint(Qs[r * QSTR + ci + 4]);
                af[mt][3] = __float_as_uint(Qs[(r + 8) * QSTR + ci + 4]);
            }
#pragma unroll
            for (int nt = 0; nt < 4; ++nt) {
                const int cn = wn * 32 + nt * 8 + gID;
                bf[nt][0] = __float_as_uint(Ks[cn * QSTR + ci]);
                bf[nt][1] = __float_as_uint(Ks[cn * QSTR + ci + 4]);
            }
#pragma unroll
            for (int mt = 0; mt < 4; ++mt)
#pragma unroll
                for (int nt = 0; nt < 4; ++nt)
                    mma8(sacc[mt][nt], af[mt], bf[nt]);
        }
        // store raw scores to Ps
#pragma unroll
        for (int mt = 0; mt < 4; ++mt) {
            const int r0 = wm * 64 + mt * 16 + gID;
#pragma unroll
            for (int nt = 0; nt < 4; ++nt) {
                const int c = wn * 32 + nt * 8 + tig * 2;
                *(float2*)&Ps[r0 * PSTR + c] = make_float2(sacc[mt][nt][0], sacc[mt][nt][1]);
                *(float2*)&Ps[(r0 + 8) * PSTR + c] = make_float2(sacc[mt][nt][2], sacc[mt][nt][3]);
            }
        }
        __syncthreads();

        // --- softmax (2 threads per row) ---
        {
            const int row = tid >> 1, half = tid & 1;
            float* pr = Ps + row * PSTR + half * 64;
            float mx = -INFINITY;
#pragma unroll
            for (int j = 0; j < 16; ++j) {
                float4 v = *(float4*)(pr + j * 4);
                mx = fmaxf(mx, fmaxf(fmaxf(v.x, v.y), fmaxf(v.z, v.w)));
            }
            mx = fmaxf(mx, __shfl_xor_sync(0xffffffffu, mx, 1));
            const float mprev = mrow[row];
            const float mnew = fmaxf(mprev, mx);
            const float al = fexp(mprev - mnew);
            float s = 0.f;
#pragma unroll
            for (int j = 0; j < 16; ++j) {
                float4 v = *(float4*)(pr + j * 4);
                float p0 = fexp(v.x - mnew), p1 = fexp(v.y - mnew);
                float p2 = fexp(v.z - mnew), p3 = fexp(v.w - mnew);
                s += (p0 + p1) + (p2 + p3);
                *(float4*)(pr + j * 4) = make_float4(f2tf(p0), f2tf(p1), f2tf(p2), f2tf(p3));
            }
            s += __shfl_xor_sync(0xffffffffu, s, 1);
            if (half == 0) {
                mrow[row] = mnew;
                lrow[row] = lrow[row] * al + s;
                arow[row] = al;
            }
        }
        __syncthreads();

        // --- rescale O, then O += P @ V ---
#pragma unroll
        for (int mt = 0; mt < 4; ++mt) {
            const float a0 = arow[wm * 64 + mt * 16 + gID];
            const float a1 = arow[wm * 64 + mt * 16 + gID + 8];
#pragma unroll
            for (int nt = 0; nt < 2; ++nt) {
                oacc[mt][nt][0] *= a0; oacc[mt][nt][1] *= a0;
                oacc[mt][nt][2] *= a1; oacc[mt][nt][3] *= a1;
            }
        }
#pragma unroll
        for (int ks = 0; ks < 16; ++ks) {
            uint32_t af[4][4], bf[2][2];
            const int ci = ks * 8 + tig;
#pragma unroll
            for (int mt = 0; mt < 4; ++mt) {
                const int r = wm * 64 + mt * 16 + gID;
                af[mt][0] = __float_as_uint(Ps[r * PSTR + ci]);
                af[mt][1] = __float_as_uint(Ps[(r + 8) * PSTR + ci]);
                af[mt][2] = __float_as_uint(Ps[r * PSTR + ci + 4]);
                af[mt][3] = __float_as_uint(Ps[(r + 8) * PSTR + ci + 4]);
            }
#pragma unroll
            for (int nt = 0; nt < 2; ++nt) {
                const int cn = wn * 16 + nt * 8 + gID;
                bf[nt][0] = __float_as_uint(Vs[ci * QSTR + cn]);
                bf[nt][1] = __float_as_uint(Vs[(ci + 4) * QSTR + cn]);
            }
#pragma unroll
            for (int mt = 0; mt < 4; ++mt)
#pragma unroll
                for (int nt = 0; nt < 2; ++nt)
                    mma8(oacc[mt][nt], af[mt], bf[nt]);
        }
    }

    // output: O / l -> [b][s][h*64+d]
#pragma unroll
    for (int mt = 0; mt < 4; ++mt) {
        const int r0 = wm * 64 + mt * 16 + gID;
        const int r1 = r0 + 8;
        const float i0 = 1.f / lrow[r0];
        const float i1 = 1.f / lrow[r1];
#pragma unroll
        for (int nt = 0; nt < 2; ++nt) {
            const int c = wn * 16 + nt * 8 + tig * 2;
            float2 v0 = make_float2(oacc[mt][nt][0] * i0, oacc[mt][nt][1] * i0);
            float2 v1 = make_float2(oacc[mt][nt][2] * i1, oacc[mt][nt][3] * i1);
            *(float2*)(Aout + ((size_t)b * SSEQ + qb * 128 + r0) * DMODEL + h * HDIM + c) = v0;
            *(float2*)(Aout + ((size_t)b * SSEQ + qb * 128 + r1) * DMODEL + h * HDIM + c) = v1;
        }
    }
}

extern "C" void kernel_launch(void* const* d_in, const int* in_sizes, int n_in,
                              void* d_out, int out_size) {
    const float* X  = (const float*)d_in[0];
    const float* Wq = (const float*)d_in[1];
    const float* bq = (const float*)d_in[2];
    const float* Wk = (const float*)d_in[3];
    const float* bk = (const float*)d_in[4];
    const float* Wv = (const float*)d_in[5];
    const float* bv = (const float*)d_in[6];
    const float* Wo = (const float*)d_in[7];
    const float* bo = (const float*)d_in[8];
    float* out = (float*)d_out;

    void *qp, *kp, *vp, *ap;
    cudaGetSymbolAddress(&qp, g_Q);
    cudaGetSymbolAddress(&kp, g_K);
    cudaGetSymbolAddress(&vp, g_V);
    cudaGetSymbolAddress(&ap, g_attn);

    const int attn_smem = (128 * QSTR * 3 + 128 * PSTR + 384) * (int)sizeof(float);
    cudaFuncSetAttribute(attn_tc, cudaFuncAttributeMaxDynamicSharedMemorySize, attn_smem);

    dim3 gg(DMODEL / 128, (BB * SSEQ) / 128, 1);  // (8, 64)
    gemm_tc<<<gg, 256>>>(X, Wq, bq, (float*)qp, 1);
    gemm_tc<<<gg, 256>>>(X, Wk, bk, (float*)kp, 1);
    gemm_tc<<<gg, 256>>>(X, Wv, bv, (float*)vp, 1);
    attn_tc<<<dim3(SSEQ / 128, NHEAD, BB), 256, attn_smem>>>(
        (const float*)qp, (const float*)kp, (const float*)vp, (float*)ap);
    gemm_tc<<<gg, 256>>>((const float*)ap, Wo, bo, out, 0);
}